// round 1
// baseline (speedup 1.0000x reference)
#include <cuda_runtime.h>

#define NX 13
#define NN 169            // 13*13
#define BOLTZ 5.67e-08f
#define WARPS_PER_BLOCK 8
#define BLOCK_THREADS 256
#define GRID_BLOCKS 1184  // 148 SMs * 8

static __device__ double g_partials[2048];

__global__ __launch_bounds__(BLOCK_THREADS)
void excess_kernel(const float* __restrict__ T,        // [B,169] (outputs, flattened)
                   const float* __restrict__ heaters,  // [B,4]
                   const float* __restrict__ interf,   // [B,4]
                   const float* __restrict__ Tenv,     // [B,169]
                   const float* __restrict__ K,        // [169,169]
                   const float* __restrict__ E,        // [169]
                   int B)
{
    __shared__ float c0[NN], cL[NN], cR[NN], cU[NN], cD[NN];
    __shared__ float sigE[NN];
    __shared__ unsigned char qsel[NN];
    __shared__ float sT[WARPS_PER_BLOCK][NN + 1];
    __shared__ float qv[WARPS_PER_BLOCK][9];
    __shared__ double blockSums[WARPS_PER_BLOCK];

    const int tid  = threadIdx.x;
    const int lane = tid & 31;
    const int wid  = tid >> 5;

    // Build per-block tables (K is L2-resident: 114 KB read by every block).
    // Band read reproduces dense K@T exactly: all nonzeros of K lie on
    // {diag, +-1, +-NX}; in-range band entries that the construction never
    // wrote are 0.0f in the dense matrix, so reading them is harmless.
    for (int n = tid; n < NN; n += BLOCK_THREADS) {
        c0[n] = K[n * NN + n];
        cL[n] = (n >= 1)      ? K[n * NN + n - 1]  : 0.f;
        cR[n] = (n + 1 < NN)  ? K[n * NN + n + 1]  : 0.f;
        cU[n] = (n >= NX)     ? K[n * NN + n - NX] : 0.f;
        cD[n] = (n + NX < NN) ? K[n * NN + n + NX] : 0.f;
        sigE[n] = BOLTZ * E[n];
        unsigned char s = 8;                       // default: Q = 0
        if      (n ==  81) s = 0;                  // heater ids
        else if (n ==  45) s = 1;
        else if (n == 120) s = 2;
        else if (n == 126) s = 3;
        else if (n ==   0) s = 4;                  // interface ids
        else if (n ==  12) s = 5;
        else if (n == 168) s = 6;
        else if (n == 156) s = 7;
        qsel[n] = s;
    }
    __syncthreads();

    float acc = 0.f;
    const int warpsTotal = GRID_BLOCKS * WARPS_PER_BLOCK;
    const int gw = blockIdx.x * WARPS_PER_BLOCK + wid;

    for (int b = gw; b < B; b += warpsTotal) {
        const float* Tb = T + (size_t)b * NN;
        #pragma unroll
        for (int k = 0; k < 6; k++) {
            int n = lane + 32 * k;
            if (n < NN) sT[wid][n] = Tb[n];
        }
        if (lane < 4)       qv[wid][lane] = heaters[(size_t)b * 4 + lane];
        else if (lane < 8)  qv[wid][lane] = interf[(size_t)b * 4 + (lane - 4)];
        else if (lane == 8) qv[wid][8]    = 0.f;
        __syncwarp();

        const float* Eb = Tenv + (size_t)b * NN;
        #pragma unroll
        for (int k = 0; k < 6; k++) {
            int n = lane + 32 * k;
            if (n < NN) {
                float t  = sT[wid][n];
                float tl = sT[wid][(n >= 1)       ? n - 1  : 0];
                float tr = sT[wid][(n + 1 < NN)   ? n + 1  : 0];
                float tu = sT[wid][(n >= NX)      ? n - NX : 0];
                float td = sT[wid][(n + NX < NN)  ? n + NX : 0];
                float cond = c0[n] * t
                           + cL[n] * tl + cR[n] * tr
                           + cU[n] * tu + cD[n] * td;
                float te  = Eb[n];
                float t2  = t * t,  te2 = te * te;
                float rad = sigE[n] * (t2 * t2 - te2 * te2);
                float ex  = cond + rad - qv[wid][qsel[n]];
                acc += fabsf(ex);
            }
        }
        __syncwarp();   // protect sT before next iteration overwrites it
    }

    // warp reduce (fp32; each lane holds only a few hundred terms)
    #pragma unroll
    for (int off = 16; off; off >>= 1)
        acc += __shfl_down_sync(0xffffffffu, acc, off);
    if (lane == 0) blockSums[wid] = (double)acc;
    __syncthreads();
    if (tid == 0) {
        double s = 0.0;
        #pragma unroll
        for (int w = 0; w < WARPS_PER_BLOCK; w++) s += blockSums[w];
        g_partials[blockIdx.x] = s;
    }
}

__global__ void finalize_kernel(float* __restrict__ out, int nPartials, double invCount)
{
    __shared__ double sm[256];
    double s = 0.0;
    for (int i = threadIdx.x; i < nPartials; i += 256) s += g_partials[i];
    sm[threadIdx.x] = s;
    __syncthreads();
    for (int off = 128; off; off >>= 1) {
        if (threadIdx.x < off) sm[threadIdx.x] += sm[threadIdx.x + off];
        __syncthreads();
    }
    if (threadIdx.x == 0) out[0] = (float)(sm[0] * invCount);
}

extern "C" void kernel_launch(void* const* d_in, const int* in_sizes, int n_in,
                              void* d_out, int out_size)
{
    const float* T       = (const float*)d_in[0];  // outputs [B,13,13]
    const float* heaters = (const float*)d_in[1];  // [B,4]
    const float* interf  = (const float*)d_in[2];  // [B,4]
    const float* Tenv    = (const float*)d_in[3];  // [B,169]
    const float* K       = (const float*)d_in[4];  // [169,169]
    const float* E       = (const float*)d_in[5];  // [169]

    const int B = in_sizes[0] / NN;

    excess_kernel<<<GRID_BLOCKS, BLOCK_THREADS>>>(T, heaters, interf, Tenv, K, E, B);

    const double invCount = 1.0 / ((double)B * (double)NN);
    finalize_kernel<<<1, 256>>>((float*)d_out, GRID_BLOCKS, invCount);
}

// round 3
// speedup vs baseline: 1.5056x; 1.5056x over previous
#include <cuda_runtime.h>

#define NX 13
#define NN 169            // 13*13
#define BOLTZ 5.67e-08f
#define WPB 8             // warps per block
#define BT 256            // block threads
#define GRID 444          // 148 SMs * 3 blocks (one full wave at occ=3)

static __device__ double g_partials[GRID];
static __device__ unsigned int g_count = 0;   // wraps back to 0 every run

__device__ __forceinline__ void load_batch(const float* __restrict__ T,
                                           const float* __restrict__ Tenv,
                                           const float* __restrict__ heaters,
                                           const float* __restrict__ interf,
                                           int b, int lane,
                                           float t[6], float te[6], float& q)
{
    const float* Tb = T    + (size_t)b * NN;
    const float* Eb = Tenv + (size_t)b * NN;
    #pragma unroll
    for (int k = 0; k < 5; k++) {
        t[k]  = Tb[lane + 32 * k];
        te[k] = Eb[lane + 32 * k];
    }
    const int n5 = lane + 160;
    t[5]  = (n5 < NN) ? Tb[n5] : 0.f;
    te[5] = (n5 < NN) ? Eb[n5] : 0.f;
    q = 0.f;
    if (lane < 4)       q = heaters[(size_t)b * 4 + lane];
    else if (lane < 8)  q = interf[(size_t)b * 4 + (lane - 4)];
    // lanes >= 8 hold 0.0 -> default selector (lane 8) yields Q = 0
}

__global__ __launch_bounds__(BT, 3)
void excess_kernel(const float* __restrict__ T,        // [B,169]
                   const float* __restrict__ heaters,  // [B,4]
                   const float* __restrict__ interf,   // [B,4]
                   const float* __restrict__ Tenv,     // [B,169]
                   const float* __restrict__ K,        // [169,169]
                   const float* __restrict__ E,        // [169]
                   float* __restrict__ out,
                   int B, double invCount)
{
    __shared__ float tc0[NN], tcL[NN], tcR[NN], tcU[NN], tcD[NN], tsE[NN];
    __shared__ float sT[WPB][NN + 7];
    __shared__ double blockSums[WPB];
    __shared__ double sm[BT];
    __shared__ bool   isLast;

    const int tid  = threadIdx.x;
    const int lane = tid & 31;
    const int wid  = tid >> 5;

    // Build band tables once per block (K stays L2-resident). All nonzeros of K
    // lie on {diag, +-1, +-NX}; in-range band entries the construction never
    // wrote are exactly 0.0f in the dense matrix, so this reproduces K@T.
    for (int n = tid; n < NN; n += BT) {
        tc0[n] = K[n * NN + n];
        tcL[n] = (n >= 1)      ? K[n * NN + n - 1]  : 0.f;
        tcR[n] = (n + 1 < NN)  ? K[n * NN + n + 1]  : 0.f;
        tcU[n] = (n >= NX)     ? K[n * NN + n - NX] : 0.f;
        tcD[n] = (n + NX < NN) ? K[n * NN + n + NX] : 0.f;
        tsE[n] = BOLTZ * E[n];
    }
    __syncthreads();

    // Hoist per-node constants into registers: lane owns nodes lane+32k, k=0..5
    float c0[6], cL[6], cR[6], cU[6], cD[6], sE[6];
    int qs[6];
    #pragma unroll
    for (int k = 0; k < 6; k++) {
        int n   = lane + 32 * k;
        int ncl = (n < NN) ? n : 0;
        c0[k] = tc0[ncl]; cL[k] = tcL[ncl]; cR[k] = tcR[ncl];
        cU[k] = tcU[ncl]; cD[k] = tcD[ncl]; sE[k] = tsE[ncl];
        int s = 8;                            // default -> Q = 0 (lane 8 of qreg)
        if      (n ==  81) s = 0;             // heater nodes
        else if (n ==  45) s = 1;
        else if (n == 120) s = 2;
        else if (n == 126) s = 3;
        else if (n ==   0) s = 4;             // interface nodes
        else if (n ==  12) s = 5;
        else if (n == 168) s = 6;
        else if (n == 156) s = 7;
        qs[k] = s;
    }

    const int stride = GRID * WPB;            // total warps
    int b = blockIdx.x * WPB + wid;

    float tA[6], teA[6], qA = 0.f;
    float tB_[6], teB[6], qB = 0.f;
    float acc = 0.f;

    if (b < B)
        load_batch(T, Tenv, heaters, interf, b, lane, tA, teA, qA);

    for (; b < B; b += stride) {
        // stage current T tile for neighbor access
        #pragma unroll
        for (int k = 0; k < 5; k++) sT[wid][lane + 32 * k] = tA[k];
        if (lane < 9) sT[wid][lane + 160] = tA[5];
        __syncwarp();

        // prefetch next batch while the current one computes (14 LDGs in flight)
        const int bn = b + stride;
        if (bn < B)
            load_batch(T, Tenv, heaters, interf, bn, lane, tB_, teB, qB);

        #pragma unroll
        for (int k = 0; k < 6; k++) {
            const int n = lane + 32 * k;
            float q_k = __shfl_sync(0xffffffffu, qA, qs[k]);   // full-warp shfl
            if (k < 5 || lane < 9) {
                float t  = tA[k];
                float tl = sT[wid][(n >= 1)      ? n - 1  : 0];
                float tr = sT[wid][(n + 1 < NN)  ? n + 1  : 0];
                float tu = sT[wid][(n >= NX)     ? n - NX : 0];
                float td = sT[wid][(n + NX < NN) ? n + NX : 0];
                float cond = fmaf(c0[k], t,
                             fmaf(cL[k], tl,
                             fmaf(cR[k], tr,
                             fmaf(cU[k], tu, cD[k] * td))));
                float te  = teA[k];
                float t2 = t * t, te2 = te * te;
                float ex = fmaf(sE[k], t2 * t2 - te2 * te2, cond - q_k);
                acc += fabsf(ex);
            }
        }
        __syncwarp();   // sT reads done before next iteration's stores

        // rotate pipeline registers
        #pragma unroll
        for (int k = 0; k < 6; k++) { tA[k] = tB_[k]; teA[k] = teB[k]; }
        qA = qB;
    }

    // warp reduce (fp32: each lane sums only ~450 O(1) terms)
    #pragma unroll
    for (int off = 16; off; off >>= 1)
        acc += __shfl_down_sync(0xffffffffu, acc, off);
    if (lane == 0) blockSums[wid] = (double)acc;
    __syncthreads();

    if (tid == 0) {
        double s = 0.0;
        #pragma unroll
        for (int w = 0; w < WPB; w++) s += blockSums[w];
        g_partials[blockIdx.x] = s;
        __threadfence();
        unsigned int old = atomicInc(&g_count, GRID - 1);  // wraps to 0 -> replay-safe
        isLast = (old == GRID - 1);
    }
    __syncthreads();

    if (isLast) {   // block-uniform branch: __syncthreads inside is safe
        double s = 0.0;
        for (int i = tid; i < GRID; i += BT) s += g_partials[i];
        sm[tid] = s;
        __syncthreads();
        for (int off = BT / 2; off; off >>= 1) {
            if (tid < off) sm[tid] += sm[tid + off];
            __syncthreads();
        }
        if (tid == 0) out[0] = (float)(sm[0] * invCount);
    }
}

extern "C" void kernel_launch(void* const* d_in, const int* in_sizes, int n_in,
                              void* d_out, int out_size)
{
    const float* T       = (const float*)d_in[0];  // outputs [B,13,13]
    const float* heaters = (const float*)d_in[1];  // [B,4]
    const float* interf  = (const float*)d_in[2];  // [B,4]
    const float* Tenv    = (const float*)d_in[3];  // [B,169]
    const float* K       = (const float*)d_in[4];  // [169,169]
    const float* E       = (const float*)d_in[5];  // [169]

    const int B = in_sizes[0] / NN;
    const double invCount = 1.0 / ((double)B * (double)NN);

    excess_kernel<<<GRID, BT>>>(T, heaters, interf, Tenv, K, E,
                                (float*)d_out, B, invCount);
}

// round 5
// speedup vs baseline: 2.1129x; 1.4034x over previous
#include <cuda_runtime.h>
#include <cstdint>

#define NX 13
#define NN 169              // 13*13
#define BOLTZ 5.67e-08f
#define WPB 8               // warps per block
#define BT 256              // block threads
#define GRID 296            // 148 SMs * 2 blocks (smem-limited occupancy)
#define GPW 4               // batches per group (4*169 floats = 2704 B, 16B aligned)
#define GFLOATS (GPW * NN)  // 676 floats per array per group
#define GBYTES (GFLOATS * 4)
#define NF4 169             // float4 transfers per array per group
#define STAGEF (2 * GFLOATS)     // one stage: [T 676][Tenv 676]
#define WCHUNK (2 * STAGEF)      // double-buffered per warp: 2704 floats
#define FRONT_GUARD 16
#define REAR_GUARD 64
#define SMEM_FLOATS (FRONT_GUARD + WPB * WCHUNK + REAR_GUARD)  // 21712
#define SMEM_BYTES (SMEM_FLOATS * 4)                           // 86848

static __device__ double g_partials[GRID];
static __device__ unsigned int g_count = 0;   // wraps to 0 every run -> replay-safe

__device__ __forceinline__ void cp16(unsigned dst, const void* src) {
    asm volatile("cp.async.cg.shared.global [%0], [%1], 16;" :: "r"(dst), "l"(src));
}
__device__ __forceinline__ void cp16z(unsigned dst, const void* src, int srcBytes) {
    // copies srcBytes (<=16), zero-fills the rest of the 16B
    asm volatile("cp.async.cg.shared.global [%0], [%1], 16, %2;"
                 :: "r"(dst), "l"(src), "r"(srcBytes));
}
__device__ __forceinline__ void cp_commit() {
    asm volatile("cp.async.commit_group;" ::: "memory");
}
__device__ __forceinline__ void cp_wait0() {
    asm volatile("cp.async.wait_group 0;" ::: "memory");
}

// Prefetch group g's T and Tenv chunks into the given stage buffer.
__device__ __forceinline__ void prefetch_group(
    const char* __restrict__ gT, const char* __restrict__ gE,
    size_t totalBytes, int g, float* stageBuf, int lane)
{
    size_t off0 = (size_t)g * GBYTES;
    unsigned dT = (unsigned)__cvta_generic_to_shared(stageBuf);
    unsigned dE = (unsigned)__cvta_generic_to_shared(stageBuf + GFLOATS);
    if (off0 + GBYTES <= totalBytes) {
        // full group: plain 16B copies
        #pragma unroll
        for (int m = 0; m < 6; m++) {
            int idx = lane + 32 * m;
            if (idx < NF4) {
                size_t o = off0 + (size_t)idx * 16;
                cp16(dT + idx * 16, gT + o);
                cp16(dE + idx * 16, gE + o);
            }
        }
    } else {
        // partial tail group: clamp source size, zero-fill remainder
        long rem = (long)totalBytes - (long)off0;
        #pragma unroll
        for (int m = 0; m < 6; m++) {
            int idx = lane + 32 * m;
            if (idx < NF4) {
                long o = (long)idx * 16;
                int sb = (int)min((long)16, max((long)0, rem - o));
                size_t so = off0 + (size_t)(sb > 0 ? o : 0);
                cp16z(dT + idx * 16, gT + so, sb);
                cp16z(dE + idx * 16, gE + so, sb);
            }
        }
    }
}

__device__ __forceinline__ float load_q(const float* __restrict__ heaters,
                                        const float* __restrict__ interf,
                                        int g, int B, int lane)
{
    // lanes 0..15: heaters of batches 4g..4g+3 (4 each); lanes 16..31: interfaces
    float q = 0.f;
    int j = g * 16 + (lane & 15);
    if (j < B * 4) q = (lane < 16) ? __ldg(heaters + j) : __ldg(interf + j);
    return q;
}

__global__ __launch_bounds__(BT)
void excess_kernel(const float* __restrict__ T,        // [B,169]
                   const float* __restrict__ heaters,  // [B,4]
                   const float* __restrict__ interf,   // [B,4]
                   const float* __restrict__ Tenv,     // [B,169]
                   const float* __restrict__ K,        // [169,169]
                   const float* __restrict__ E,        // [169]
                   float* __restrict__ out,
                   int B, double invCount)
{
    extern __shared__ float smem[];
    __shared__ double blockSums[WPB];
    __shared__ double smr[BT];
    __shared__ bool   isLast;

    const int tid  = threadIdx.x;
    const int lane = tid & 31;
    const int wid  = tid >> 5;

    // Zero all dynamic smem once: guards + buffers start finite (no NaN ever).
    for (int i = tid; i < SMEM_FLOATS; i += BT) smem[i] = 0.f;
    __syncthreads();

    float* warpBuf = smem + FRONT_GUARD + wid * WCHUNK;

    // Per-lane per-k constants read straight from K/E (L2-resident).
    // Band read reproduces dense K@T exactly: all nonzeros lie on {diag,+-1,+-NX}.
    float c0[6], cL[6], cR[6], cU[6], cD[6], sE[6], qm[6];
    int qo[6];
    #pragma unroll
    for (int k = 0; k < 6; k++) {
        int n = lane + 32 * k;
        bool in = (n < NN);
        c0[k] = in               ? __ldg(K + n * NN + n)      : 0.f;
        cL[k] = (in && n >= 1)   ? __ldg(K + n * NN + n - 1)  : 0.f;
        cR[k] = (in && n+1 < NN) ? __ldg(K + n * NN + n + 1)  : 0.f;
        cU[k] = (in && n >= NX)  ? __ldg(K + n * NN + n - NX) : 0.f;
        cD[k] = (in && n+NX < NN)? __ldg(K + n * NN + n + NX) : 0.f;
        sE[k] = in               ? BOLTZ * __ldg(E + n)       : 0.f;
        int o = 0; float m = 0.f;
        if      (n ==  81) { o = 0;  m = 1.f; }   // heaters[:,0]
        else if (n ==  45) { o = 1;  m = 1.f; }   // heaters[:,1]
        else if (n == 120) { o = 2;  m = 1.f; }   // heaters[:,2]
        else if (n == 126) { o = 3;  m = 1.f; }   // heaters[:,3]
        else if (n ==   0) { o = 16; m = 1.f; }   // interfaces[:,0]
        else if (n ==  12) { o = 17; m = 1.f; }   // interfaces[:,1]
        else if (n == 168) { o = 18; m = 1.f; }   // interfaces[:,2]
        else if (n == 156) { o = 19; m = 1.f; }   // interfaces[:,3]
        qo[k] = o; qm[k] = m;
    }

    const char* gT = (const char*)T;
    const char* gE = (const char*)Tenv;
    const size_t totalBytes = (size_t)B * NN * 4;
    const int nG = (B + GPW - 1) / GPW;          // total groups
    const int ws = GRID * WPB;                   // warp stride (in groups)

    int g = blockIdx.x * WPB + wid;
    int stage = 0;
    float qreg = 0.f, acc = 0.f;

    if (g < nG) {
        prefetch_group(gT, gE, totalBytes, g, warpBuf, lane);
        qreg = load_q(heaters, interf, g, B, lane);
    }
    cp_commit();

    for (; g < nG; g += ws) {
        cp_wait0();
        __syncwarp();

        const int gn = g + ws;
        if (gn < nG)
            prefetch_group(gT, gE, totalBytes, gn, warpBuf + (stage ^ 1) * STAGEF, lane);
        cp_commit();
        float qn = (gn < nG) ? load_q(heaters, interf, gn, B, lane) : 0.f;

        const float* buf = warpBuf + stage * STAGEF;
        #pragma unroll
        for (int bb = 0; bb < GPW; bb++) {
            const float* p = buf + bb * NN + lane;   // immediate offsets from here
            #pragma unroll
            for (int k = 0; k < 6; k++) {
                const int o = 32 * k;
                float t  = p[o];
                float tl = p[o - 1];
                float tr = p[o + 1];
                float tu = p[o - NX];
                float td = p[o + NX];
                float te = p[o + GFLOATS];
                float cond = c0[k] * t;
                cond = fmaf(cL[k], tl, cond);
                cond = fmaf(cR[k], tr, cond);
                cond = fmaf(cU[k], tu, cond);
                cond = fmaf(cD[k], td, cond);
                float qk = qm[k] * __shfl_sync(0xffffffffu, qreg, qo[k] + bb * 4);
                float t2 = t * t, te2 = te * te;
                float d  = fmaf(t2, t2, -(te2 * te2));
                float ex = fmaf(sE[k], d, cond - qk);
                acc += fabsf(ex);
            }
        }
        stage ^= 1;
        qreg = qn;
    }

    // warp reduce (fp32: each lane sums only ~700 O(1) terms)
    #pragma unroll
    for (int off = 16; off; off >>= 1)
        acc += __shfl_down_sync(0xffffffffu, acc, off);
    if (lane == 0) blockSums[wid] = (double)acc;
    __syncthreads();

    if (tid == 0) {
        double s = 0.0;
        #pragma unroll
        for (int w = 0; w < WPB; w++) s += blockSums[w];
        g_partials[blockIdx.x] = s;
        __threadfence();
        unsigned int old = atomicInc(&g_count, GRID - 1);  // wraps -> replay-safe
        isLast = (old == GRID - 1);
    }
    __syncthreads();

    if (isLast) {
        double s = 0.0;
        for (int i = tid; i < GRID; i += BT) s += g_partials[i];
        smr[tid] = s;
        __syncthreads();
        for (int off = BT / 2; off; off >>= 1) {
            if (tid < off) smr[tid] += smr[tid + off];
            __syncthreads();
        }
        if (tid == 0) out[0] = (float)(smr[0] * invCount);
    }
}

extern "C" void kernel_launch(void* const* d_in, const int* in_sizes, int n_in,
                              void* d_out, int out_size)
{
    const float* T       = (const float*)d_in[0];  // outputs [B,13,13]
    const float* heaters = (const float*)d_in[1];  // [B,4]
    const float* interf  = (const float*)d_in[2];  // [B,4]
    const float* Tenv    = (const float*)d_in[3];  // [B,169]
    const float* K       = (const float*)d_in[4];  // [169,169]
    const float* E       = (const float*)d_in[5];  // [169]

    const int B = in_sizes[0] / NN;
    const double invCount = 1.0 / ((double)B * (double)NN);

    cudaFuncSetAttribute(excess_kernel,
                         cudaFuncAttributeMaxDynamicSharedMemorySize, SMEM_BYTES);

    excess_kernel<<<GRID, BT, SMEM_BYTES>>>(T, heaters, interf, Tenv, K, E,
                                            (float*)d_out, B, invCount);
}